// round 14
// baseline (speedup 1.0000x reference)
#include <cuda_runtime.h>
#include <cuda_bf16.h>
#include <stdint.h>

#define INPUT_DIM  1024
#define LATENT_DIM 256
#define NUM_EMB    8192
#define BATCH      8192

#define MARGIN 0.02f
#define CAP    256

// ------------------------- device scratch (allocation-free) ----------------
__device__ float               g_inv_norm[NUM_EMB];
__device__ float               g_zinv[BATCH];
__device__ unsigned int        g_amax[BATCH];
__device__ unsigned int        g_ccnt[BATCH];
__device__ __align__(16) uint2 g_cand[(size_t)BATCH * CAP];
__device__ __align__(16) __nv_bfloat16 g_emb_bf16[NUM_EMB * LATENT_DIM];  // hi plane
__device__ __align__(16) __nv_bfloat16 g_emb_l[NUM_EMB * LATENT_DIM];    // lo plane
__device__ __align__(16) __nv_bfloat16 g_z_bf16[BATCH * LATENT_DIM];
__device__ __align__(16) __nv_bfloat16 g_dw_h[INPUT_DIM * LATENT_DIM];
__device__ __align__(16) __nv_bfloat16 g_dw_l[INPUT_DIM * LATENT_DIM];
__device__ __align__(16) float g_recon[(size_t)NUM_EMB * INPUT_DIM];      // 32 MB

// ------------------------- helpers -----------------------------------------
__device__ __forceinline__ uint32_t smem_u32(const void* p) {
    uint32_t a;
    asm("{ .reg .u64 t; cvta.to.shared.u64 t, %1; cvt.u32.u64 %0, t; }" : "=r"(a) : "l"(p));
    return a;
}
__device__ __forceinline__ unsigned int float_key(float f) {
    unsigned int u = __float_as_uint(f);
    return (u & 0x80000000u) ? ~u : (u | 0x80000000u);
}
__device__ __forceinline__ float key_to_float(unsigned int k) {
    return (k & 0x80000000u) ? __uint_as_float(k ^ 0x80000000u)
                             : __uint_as_float(~k);
}
__device__ __forceinline__ void mma_bf16(float* d, const uint32_t* a, const uint32_t* b) {
    asm volatile(
        "mma.sync.aligned.m16n8k16.row.col.f32.bf16.bf16.f32 "
        "{%0,%1,%2,%3}, {%4,%5,%6,%7}, {%8,%9}, {%0,%1,%2,%3};"
        : "+f"(d[0]), "+f"(d[1]), "+f"(d[2]), "+f"(d[3])
        : "r"(a[0]), "r"(a[1]), "r"(a[2]), "r"(a[3]), "r"(b[0]), "r"(b[1]));
}
__device__ __forceinline__ void ldsm_x4(uint32_t& r0, uint32_t& r1,
                                        uint32_t& r2, uint32_t& r3, uint32_t addr) {
    asm volatile("ldmatrix.sync.aligned.m8n8.x4.shared.b16 {%0,%1,%2,%3}, [%4];"
                 : "=r"(r0), "=r"(r1), "=r"(r2), "=r"(r3) : "r"(addr));
}
__device__ __forceinline__ unsigned int pack_bf16x2(float lo, float hi) {
    __nv_bfloat162 h = __floats2bfloat162_rn(lo, hi);
    return *reinterpret_cast<unsigned int*>(&h);
}
__device__ __forceinline__ void split2(float v0, float v1,
                                       unsigned int& hw, unsigned int& lw) {
    __nv_bfloat16 h0 = __float2bfloat16(v0);
    __nv_bfloat16 h1 = __float2bfloat16(v1);
    float r0 = v0 - __bfloat162float(h0);
    float r1 = v1 - __bfloat162float(h1);
    __nv_bfloat162 hh; hh.x = h0; hh.y = h1;
    hw = *reinterpret_cast<unsigned int*>(&hh);
    lw = pack_bf16x2(r0, r1);
}

// ---------------------------------------------------------------------------
// init (merged): emb hi/lo planes + inv-norm + counters; dec_w hi/lo planes
// ---------------------------------------------------------------------------
__global__ void __launch_bounds__(256)
init_kernel(const float* __restrict__ emb, const float* __restrict__ dw) {
    const int warp = threadIdx.x >> 5, lane = threadIdx.x & 31;
    if (blockIdx.x < NUM_EMB / 8) {
        const int row = blockIdx.x * 8 + warp;
        const float4* p = reinterpret_cast<const float4*>(emb + (size_t)row * LATENT_DIM);
        float4 a = p[lane * 2], b = p[lane * 2 + 1];
        uint4 oh, ol;
        split2(a.x, a.y, oh.x, ol.x); split2(a.z, a.w, oh.y, ol.y);
        split2(b.x, b.y, oh.z, ol.z); split2(b.z, b.w, oh.w, ol.w);
        *reinterpret_cast<uint4*>(g_emb_bf16 + (size_t)row * LATENT_DIM + lane * 8) = oh;
        *reinterpret_cast<uint4*>(g_emb_l    + (size_t)row * LATENT_DIM + lane * 8) = ol;
        float s = a.x*a.x + a.y*a.y + a.z*a.z + a.w*a.w
                + b.x*b.x + b.y*b.y + b.z*b.z + b.w*b.w;
        #pragma unroll
        for (int off = 16; off > 0; off >>= 1) s += __shfl_xor_sync(0xFFFFFFFFu, s, off);
        if (lane == 0) {
            g_inv_norm[row] = rsqrtf(s);
            g_amax[row] = 0u;
            g_ccnt[row] = 0u;
        }
    } else {
        const int row = (blockIdx.x - NUM_EMB / 8) * 8 + warp;
        const float4* p = reinterpret_cast<const float4*>(dw + (size_t)row * LATENT_DIM);
        float4 a = p[lane * 2], b = p[lane * 2 + 1];
        uint4 oh, ol;
        split2(a.x, a.y, oh.x, ol.x); split2(a.z, a.w, oh.y, ol.y);
        split2(b.x, b.y, oh.z, ol.z); split2(b.z, b.w, oh.w, ol.w);
        *reinterpret_cast<uint4*>(g_dw_h + (size_t)row * LATENT_DIM + lane * 8) = oh;
        *reinterpret_cast<uint4*>(g_dw_l + (size_t)row * LATENT_DIM + lane * 8) = ol;
    }
}

// z -> bf16 + 1/|z| (warp per row)
__global__ void __launch_bounds__(256)
convert_z_kernel(const float* __restrict__ z) {
    const int warp = threadIdx.x >> 5, lane = threadIdx.x & 31;
    const int row  = blockIdx.x * 8 + warp;
    const float4* p = reinterpret_cast<const float4*>(z + (size_t)row * LATENT_DIM);
    float4 a = p[lane * 2], b = p[lane * 2 + 1];
    uint4 o;
    o.x = pack_bf16x2(a.x, a.y); o.y = pack_bf16x2(a.z, a.w);
    o.z = pack_bf16x2(b.x, b.y); o.w = pack_bf16x2(b.z, b.w);
    *reinterpret_cast<uint4*>(g_z_bf16 + (size_t)row * LATENT_DIM + lane * 8) = o;
    float s = a.x*a.x + a.y*a.y + a.z*a.z + a.w*a.w
            + b.x*b.x + b.y*b.y + b.z*b.z + b.w*b.w;
    #pragma unroll
    for (int off = 16; off > 0; off >>= 1) s += __shfl_xor_sync(0xFFFFFFFFu, s, off);
    if (lane == 0) g_zinv[row] = rsqrtf(s);
}

// ---------------------------------------------------------------------------
// encoder fp32 SIMT GEMM: CTA 128x64, per-thread 8x4 (unchanged)
// ---------------------------------------------------------------------------
constexpr int EBK = 16, EBMP = 132, EBNP = 68;

__global__ void __launch_bounds__(256, 2)
sgemm_encoder(const float* __restrict__ A, const float* __restrict__ B,
              const float* __restrict__ bias, float* __restrict__ C,
              int M, int N, int K) {
    __shared__ __align__(16) float As[EBK * EBMP];
    __shared__ __align__(16) float Bs[EBK * EBNP];
    const int tid  = threadIdx.x;
    const int tx   = tid & 15;
    const int ty   = tid >> 4;
    const int row0 = blockIdx.y * 128;
    const int col0 = blockIdx.x * 64;
    float acc[8][4] = {};
    for (int k0 = 0; k0 < K; k0 += EBK) {
        #pragma unroll
        for (int it = 0; it < 2; it++) {
            int idx = tid + it * 256;
            int r   = idx >> 2;
            int kq  = (idx & 3) * 4;
            float4 v = *reinterpret_cast<const float4*>(&A[(size_t)(row0 + r) * K + k0 + kq]);
            As[(kq + 0) * EBMP + r] = v.x;
            As[(kq + 1) * EBMP + r] = v.y;
            As[(kq + 2) * EBMP + r] = v.z;
            As[(kq + 3) * EBMP + r] = v.w;
        }
        {
            int r  = tid >> 2;
            int kq = (tid & 3) * 4;
            float4 v = *reinterpret_cast<const float4*>(&B[(size_t)(col0 + r) * K + k0 + kq]);
            Bs[(kq + 0) * EBNP + r] = v.x;
            Bs[(kq + 1) * EBNP + r] = v.y;
            Bs[(kq + 2) * EBNP + r] = v.z;
            Bs[(kq + 3) * EBNP + r] = v.w;
        }
        __syncthreads();
        #pragma unroll
        for (int kk = 0; kk < EBK; kk++) {
            float rm[8], rn[4];
            float4 a0 = *reinterpret_cast<const float4*>(&As[kk * EBMP + ty * 8]);
            float4 a1 = *reinterpret_cast<const float4*>(&As[kk * EBMP + ty * 8 + 4]);
            float4 b0 = *reinterpret_cast<const float4*>(&Bs[kk * EBNP + tx * 4]);
            rm[0]=a0.x; rm[1]=a0.y; rm[2]=a0.z; rm[3]=a0.w;
            rm[4]=a1.x; rm[5]=a1.y; rm[6]=a1.z; rm[7]=a1.w;
            rn[0]=b0.x; rn[1]=b0.y; rn[2]=b0.z; rn[3]=b0.w;
            #pragma unroll
            for (int m = 0; m < 8; m++)
                #pragma unroll
                for (int n = 0; n < 4; n++)
                    acc[m][n] = fmaf(rm[m], rn[n], acc[m][n]);
        }
        __syncthreads();
    }
    int c = col0 + tx * 4;
    float4 bv = *reinterpret_cast<const float4*>(&bias[c]);
    #pragma unroll
    for (int m = 0; m < 8; m++) {
        int r = row0 + ty * 8 + m;
        float4 v;
        v.x = acc[m][0] + bv.x;
        v.y = acc[m][1] + bv.y;
        v.z = acc[m][2] + bv.z;
        v.w = acc[m][3] + bv.w;
        *reinterpret_cast<float4*>(&C[(size_t)r * N + c]) = v;
    }
}

// ---------------------------------------------------------------------------
// shared tile constants + cp.async loader
// ---------------------------------------------------------------------------
constexpr int SKH  = 72;
constexpr int HBUF = 128 * SKH;

__device__ __forceinline__ void cp_chunk(const __nv_bfloat16* __restrict__ g,
                                         int gr0, int k0, __nv_bfloat16* sm, int tid) {
    #pragma unroll
    for (int it = 0; it < 4; it++) {
        int idx = tid + it * 256;
        int r   = idx >> 3;
        int c   = idx & 7;
        uint32_t dst = smem_u32(&sm[r * SKH + c * 8]);
        size_t src = __cvta_generic_to_global(g + (size_t)(gr0 + r) * 256 + k0 + c * 8);
        asm volatile("cp.async.ca.shared.global [%0], [%1], 16;" :: "r"(dst), "l"(src));
    }
}

// ---------------------------------------------------------------------------
// HMMA bf16 score GEMM — R10 8-warp config (best measured), ldmatrix loads
// ---------------------------------------------------------------------------
__global__ void __launch_bounds__(256, 2)
hmma_scores_kernel() {
    extern __shared__ __align__(16) __nv_bfloat16 dyn[];
    __nv_bfloat16* sA = dyn;
    __nv_bfloat16* sB = dyn + 2 * HBUF;
    __shared__ float s_inv[128];
    __shared__ float s_zinv[128];
    __shared__ unsigned int s_amax[128];

    const int tid = threadIdx.x, wid = tid >> 5, lane = tid & 31;
    const int row0 = blockIdx.y * 128, col0 = blockIdx.x * 128;
    const int wm = (wid & 3) * 32, wn = (wid >> 2) * 64;
    const int g = lane >> 2, q = lane & 3;

    const int lane7 = lane & 7;
    const int a_row = wm + lane7 + ((lane >> 3) & 1) * 8;
    const int a_col = (lane >> 4) * 8;
    const int b_row = wn + lane7 + (lane >> 4) * 8;
    const int b_col = ((lane >> 3) & 1) * 8;

    if (tid < 128) {
        s_inv[tid]  = g_inv_norm[col0 + tid];
        s_zinv[tid] = g_zinv[row0 + tid];
        s_amax[tid] = 0u;
    }

    cp_chunk(g_z_bf16,   row0, 0, sA, tid);
    cp_chunk(g_emb_bf16, col0, 0, sB, tid);
    asm volatile("cp.async.commit_group;" ::: "memory");

    float acc[2][8][4] = {};
    #pragma unroll
    for (int kc = 0; kc < 4; kc++) {
        if (kc < 3) {
            cp_chunk(g_z_bf16,   row0, (kc + 1) * 64, sA + ((kc + 1) & 1) * HBUF, tid);
            cp_chunk(g_emb_bf16, col0, (kc + 1) * 64, sB + ((kc + 1) & 1) * HBUF, tid);
            asm volatile("cp.async.commit_group;" ::: "memory");
            asm volatile("cp.async.wait_group 1;" ::: "memory");
        } else {
            asm volatile("cp.async.wait_group 0;" ::: "memory");
        }
        __syncthreads();

        const uint32_t aBase = smem_u32(sA + (kc & 1) * HBUF);
        const uint32_t bBase = smem_u32(sB + (kc & 1) * HBUF);
        #pragma unroll
        for (int k16 = 0; k16 < 4; k16++) {
            uint32_t a[2][4];
            #pragma unroll
            for (int mf = 0; mf < 2; mf++)
                ldsm_x4(a[mf][0], a[mf][1], a[mf][2], a[mf][3],
                        aBase + ((a_row + mf * 16) * SKH + k16 * 16 + a_col) * 2);
            uint32_t b[8][2];
            #pragma unroll
            for (int p = 0; p < 4; p++)
                ldsm_x4(b[2*p][0], b[2*p][1], b[2*p+1][0], b[2*p+1][1],
                        bBase + ((b_row + p * 16) * SKH + k16 * 16 + b_col) * 2);
            #pragma unroll
            for (int mf = 0; mf < 2; mf++)
                #pragma unroll
                for (int nf = 0; nf < 8; nf++)
                    mma_bf16(acc[mf][nf], a[mf], b[nf]);
        }
        __syncthreads();
    }

    #pragma unroll
    for (int mf = 0; mf < 2; mf++) {
        #pragma unroll
        for (int rp = 0; rp < 2; rp++) {
            int lrow = wm + mf * 16 + g + rp * 8;
            float zi = s_zinv[lrow];
            unsigned int bestk = 0u;
            #pragma unroll
            for (int nf = 0; nf < 8; nf++) {
                int lcol = wn + nf * 8 + q * 2;
                float s0 = acc[mf][nf][rp * 2 + 0] * s_inv[lcol + 0] * zi;
                float s1 = acc[mf][nf][rp * 2 + 1] * s_inv[lcol + 1] * zi;
                unsigned int k0 = float_key(s0), k1 = float_key(s1);
                bestk = bestk > k0 ? bestk : k0;
                bestk = bestk > k1 ? bestk : k1;
            }
            unsigned int o1 = __shfl_xor_sync(0xFFFFFFFFu, bestk, 1);
            bestk = bestk > o1 ? bestk : o1;
            unsigned int o2 = __shfl_xor_sync(0xFFFFFFFFu, bestk, 2);
            bestk = bestk > o2 ? bestk : o2;
            if (q == 0) atomicMax(&s_amax[lrow], bestk);
        }
    }
    __syncthreads();

    if (tid < 128) {
        unsigned int old = atomicMax(&g_amax[row0 + tid], s_amax[tid]);
        if (old > s_amax[tid]) s_amax[tid] = old;
    }
    __syncthreads();

    #pragma unroll
    for (int mf = 0; mf < 2; mf++) {
        #pragma unroll
        for (int rp = 0; rp < 2; rp++) {
            int lrow = wm + mf * 16 + g + rp * 8;
            int grow = row0 + lrow;
            float zi = s_zinv[lrow];
            float lth = key_to_float(s_amax[lrow]) - MARGIN;
            #pragma unroll
            for (int nf = 0; nf < 8; nf++) {
                int lcol = wn + nf * 8 + q * 2;
                #pragma unroll
                for (int h = 0; h < 2; h++) {
                    float s = acc[mf][nf][rp * 2 + h] * s_inv[lcol + h] * zi;
                    if (s >= lth) {
                        unsigned int pos = atomicAdd(&g_ccnt[grow], 1u);
                        if (pos < CAP)
                            g_cand[(size_t)grow * CAP + pos] =
                                make_uint2(__float_as_uint(s), (unsigned)(col0 + lcol + h));
                    }
                }
            }
        }
    }
}

// ---------------------------------------------------------------------------
// recon GEMM (off critical path): g_recon = emb @ dec_w^T + dec_b
// 3-pass split-bf16 HMMA (ah*bh + al*bh + ah*bl), R10-style serialized loads.
// Bit-identical to decoder(zq) since zq rows == emb rows.
// ---------------------------------------------------------------------------
__global__ void __launch_bounds__(256, 2)
hmma_recon_kernel(const float* __restrict__ bias) {
    extern __shared__ __align__(16) __nv_bfloat16 dyn[];
    __nv_bfloat16* sAh = dyn;
    __nv_bfloat16* sAl = dyn + HBUF;
    __nv_bfloat16* sBh = dyn + 2 * HBUF;
    __nv_bfloat16* sBl = dyn + 3 * HBUF;
    __shared__ float s_bias[128];

    const int tid = threadIdx.x, wid = tid >> 5, lane = tid & 31;
    const int row0 = blockIdx.y * 128, col0 = blockIdx.x * 128;
    const int wm = (wid & 3) * 32, wn = (wid >> 2) * 64;
    const int g = lane >> 2, q = lane & 3;

    const int lane7 = lane & 7;
    const int a_row = wm + lane7 + ((lane >> 3) & 1) * 8;
    const int a_col = (lane >> 4) * 8;
    const int b_row = wn + lane7 + (lane >> 4) * 8;
    const int b_col = ((lane >> 3) & 1) * 8;

    if (tid < 128) s_bias[tid] = bias[col0 + tid];

    const uint32_t ahB = smem_u32(sAh), alB = smem_u32(sAl);
    const uint32_t bhB = smem_u32(sBh), blB = smem_u32(sBl);

    float acc[2][8][4] = {};
    #pragma unroll
    for (int kc = 0; kc < 4; kc++) {
        cp_chunk(g_emb_bf16, row0, kc * 64, sAh, tid);
        cp_chunk(g_emb_l,    row0, kc * 64, sAl, tid);
        cp_chunk(g_dw_h,     col0, kc * 64, sBh, tid);
        cp_chunk(g_dw_l,     col0, kc * 64, sBl, tid);
        asm volatile("cp.async.commit_group;" ::: "memory");
        asm volatile("cp.async.wait_group 0;" ::: "memory");
        __syncthreads();

        #pragma unroll
        for (int k16 = 0; k16 < 4; k16++) {
            uint32_t ah[2][4], al[2][4];
            #pragma unroll
            for (int mf = 0; mf < 2; mf++) {
                uint32_t off = ((a_row + mf * 16) * SKH + k16 * 16 + a_col) * 2;
                ldsm_x4(ah[mf][0], ah[mf][1], ah[mf][2], ah[mf][3], ahB + off);
                ldsm_x4(al[mf][0], al[mf][1], al[mf][2], al[mf][3], alB + off);
            }
            uint32_t b[8][2];
            #pragma unroll
            for (int p = 0; p < 4; p++)
                ldsm_x4(b[2*p][0], b[2*p][1], b[2*p+1][0], b[2*p+1][1],
                        bhB + ((b_row + p * 16) * SKH + k16 * 16 + b_col) * 2);
            #pragma unroll
            for (int mf = 0; mf < 2; mf++)
                #pragma unroll
                for (int nf = 0; nf < 8; nf++) {
                    mma_bf16(acc[mf][nf], ah[mf], b[nf]);
                    mma_bf16(acc[mf][nf], al[mf], b[nf]);
                }
            #pragma unroll
            for (int p = 0; p < 4; p++)
                ldsm_x4(b[2*p][0], b[2*p][1], b[2*p+1][0], b[2*p+1][1],
                        blB + ((b_row + p * 16) * SKH + k16 * 16 + b_col) * 2);
            #pragma unroll
            for (int mf = 0; mf < 2; mf++)
                #pragma unroll
                for (int nf = 0; nf < 8; nf++)
                    mma_bf16(acc[mf][nf], ah[mf], b[nf]);
        }
        __syncthreads();
    }

    #pragma unroll
    for (int mf = 0; mf < 2; mf++) {
        #pragma unroll
        for (int rp = 0; rp < 2; rp++) {
            int grow = row0 + wm + mf * 16 + g + rp * 8;
            float* out = g_recon + (size_t)grow * INPUT_DIM + col0;
            #pragma unroll
            for (int nf = 0; nf < 8; nf++) {
                int lcol = wn + nf * 8 + q * 2;
                float2 v;
                v.x = acc[mf][nf][rp * 2 + 0] + s_bias[lcol + 0];
                v.y = acc[mf][nf][rp * 2 + 1] + s_bias[lcol + 1];
                *reinterpret_cast<float2*>(out + lcol) = v;
            }
        }
    }
}

// ---------------------------------------------------------------------------
// select: candidate filter + exact fp32 rescore + gather zq AND x_recon row
// ---------------------------------------------------------------------------
__device__ __forceinline__ unsigned long long
warp_rescore(int k, const float* __restrict__ emb,
             float4 zf0, float4 zf1, int lane) {
    const float4* e = reinterpret_cast<const float4*>(emb + (size_t)k * LATENT_DIM);
    float4 e0 = e[lane * 2], e1 = e[lane * 2 + 1];
    float d = e0.x*zf0.x + e0.y*zf0.y + e0.z*zf0.z + e0.w*zf0.w
            + e1.x*zf1.x + e1.y*zf1.y + e1.z*zf1.z + e1.w*zf1.w;
    #pragma unroll
    for (int off = 16; off > 0; off >>= 1)
        d += __shfl_xor_sync(0xFFFFFFFFu, d, off);
    float cosv = d * g_inv_norm[k];
    return ((unsigned long long)float_key(cosv) << 32) |
           (unsigned long long)(0xFFFFFFFFu - (unsigned)k);
}

__global__ void __launch_bounds__(256)
select_gather_kernel(const float* __restrict__ z, const float* __restrict__ emb,
                     float* __restrict__ xr_out,
                     float* __restrict__ zq_out, float* __restrict__ idx_out) {
    const int warp = threadIdx.x >> 5, lane = threadIdx.x & 31;
    const int row  = blockIdx.x * 8 + warp;

    const float4* zrow = reinterpret_cast<const float4*>(z + (size_t)row * LATENT_DIM);
    float4 zf0 = zrow[lane * 2], zf1 = zrow[lane * 2 + 1];

    float maxf = key_to_float(g_amax[row]);
    float thresh = maxf - MARGIN;
    unsigned int cnt = g_ccnt[row];
    bool fullscan = !(thresh >= -4.0f) || !(thresh <= 1.0f) || (cnt > CAP);

    unsigned long long best = 0ull;
    if (!fullscan) {
        const uint2* clist = g_cand + (size_t)row * CAP;
        for (unsigned int base = 0; base < cnt; base += 32) {
            unsigned int i = base + lane;
            unsigned int col = 0; bool cand = false;
            if (i < cnt) {
                uint2 e = clist[i];
                float s = __uint_as_float(e.x);
                if (!(s < thresh)) { cand = true; col = e.y; }
            }
            unsigned int m = __ballot_sync(0xFFFFFFFFu, cand);
            while (m) {
                int src = __ffs(m) - 1; m &= m - 1;
                int k = (int)__shfl_sync(0xFFFFFFFFu, col, src);
                unsigned long long key = warp_rescore(k, emb, zf0, zf1, lane);
                best = best > key ? best : key;
            }
        }
    } else {
        for (int k = 0; k < NUM_EMB; k++) {
            unsigned long long key = warp_rescore(k, emb, zf0, zf1, lane);
            best = best > key ? best : key;
        }
    }

    unsigned int widx = 0xFFFFFFFFu - (unsigned int)(best & 0xFFFFFFFFull);
    if (widx >= NUM_EMB) widx = 0;
    if (lane == 0) idx_out[row] = (float)widx;

    // zq gather (256 floats)
    const float4* e = reinterpret_cast<const float4*>(emb + (size_t)widx * LATENT_DIM);
    float4* dst = reinterpret_cast<float4*>(zq_out + (size_t)row * LATENT_DIM);
    dst[lane * 2]     = e[lane * 2];
    dst[lane * 2 + 1] = e[lane * 2 + 1];

    // x_recon gather (1024 floats) from precomputed recon table
    const float4* rsrc = reinterpret_cast<const float4*>(g_recon + (size_t)widx * INPUT_DIM);
    float4* rdst = reinterpret_cast<float4*>(xr_out + (size_t)row * INPUT_DIM);
    #pragma unroll
    for (int i = 0; i < 8; i++)
        rdst[i * 32 + lane] = rsrc[i * 32 + lane];
}

// ---------------------------------------------------------------------------
// launch: recon GEMM forked onto a side stream (overlaps encoder+scores)
// ---------------------------------------------------------------------------
extern "C" void kernel_launch(void* const* d_in, const int* in_sizes, int n_in,
                              void* d_out, int out_size) {
    const float* x     = (const float*)d_in[0];
    const float* enc_w = (const float*)d_in[1];
    const float* enc_b = (const float*)d_in[2];
    const float* emb   = (const float*)d_in[3];
    const float* dec_w = (const float*)d_in[4];
    const float* dec_b = (const float*)d_in[5];

    float* out     = (float*)d_out;
    float* x_recon = out;
    float* z       = x_recon + (size_t)BATCH * INPUT_DIM;
    float* zq      = z + (size_t)BATCH * LATENT_DIM;
    float* idxf    = zq + (size_t)BATCH * LATENT_DIM;

    const int HSMEM = 4 * HBUF * (int)sizeof(__nv_bfloat16);   // 73728 B
    cudaFuncSetAttribute(hmma_scores_kernel,
                         cudaFuncAttributeMaxDynamicSharedMemorySize, HSMEM);
    cudaFuncSetAttribute(hmma_recon_kernel,
                         cudaFuncAttributeMaxDynamicSharedMemorySize, HSMEM);

    cudaStream_t s2;
    cudaStreamCreateWithFlags(&s2, cudaStreamNonBlocking);
    cudaEvent_t eInit, eRecon;
    cudaEventCreateWithFlags(&eInit, cudaEventDisableTiming);
    cudaEventCreateWithFlags(&eRecon, cudaEventDisableTiming);

    // 0) emb hi/lo + inv-norms + counters; dec_w hi/lo (main stream)
    init_kernel<<<NUM_EMB / 8 + INPUT_DIM / 8, 256>>>(emb, dec_w);
    cudaEventRecord(eInit, 0);

    // side stream: recon table = emb @ dec_w^T + dec_b (independent of x)
    cudaStreamWaitEvent(s2, eInit, 0);
    hmma_recon_kernel<<<dim3(INPUT_DIM / 128, NUM_EMB / 128), 256, HSMEM, s2>>>(dec_b);
    cudaEventRecord(eRecon, s2);

    // 1) encoder (fp32 SIMT): z = x @ enc_w^T + enc_b
    sgemm_encoder<<<dim3(LATENT_DIM / 64, BATCH / 128), 256>>>(
        x, enc_w, enc_b, z, BATCH, LATENT_DIM, INPUT_DIM);

    // 2) z -> bf16 + 1/|z|
    convert_z_kernel<<<BATCH / 8, 256>>>(z);

    // 3) HMMA bf16 cosine scores -> per-row max + candidate lists
    hmma_scores_kernel<<<dim3(NUM_EMB / 128, BATCH / 128), 256, HSMEM>>>();

    // join: recon table must be ready before select gathers x_recon
    cudaStreamWaitEvent(0, eRecon, 0);

    // 4) select + exact rescore + gather idx, zq, x_recon
    select_gather_kernel<<<BATCH / 8, 256>>>(z, emb, x_recon, zq, idxf);

    cudaEventDestroy(eInit);
    cudaEventDestroy(eRecon);
    cudaStreamDestroy(s2);
}

// round 15
// speedup vs baseline: 1.1449x; 1.1449x over previous
#include <cuda_runtime.h>
#include <cuda_bf16.h>
#include <stdint.h>

#define INPUT_DIM  1024
#define LATENT_DIM 256
#define NUM_EMB    8192
#define BATCH      8192

#define MARGIN 0.02f
#define CAP    256

// ------------------------- device scratch (allocation-free) ----------------
__device__ float               g_inv_norm[NUM_EMB];
__device__ float               g_znorm2[BATCH];
__device__ unsigned int        g_amax[BATCH];
__device__ unsigned int        g_ccnt[BATCH];
__device__ __align__(16) uint2 g_cand[(size_t)BATCH * CAP];
__device__ __align__(16) __nv_bfloat16 g_emb_bf16[NUM_EMB * LATENT_DIM];
__device__ __align__(16) __nv_bfloat16 g_z_bf16[BATCH * LATENT_DIM];
__device__ __align__(16) __nv_bfloat16 g_zq_h[BATCH * LATENT_DIM];
__device__ __align__(16) __nv_bfloat16 g_zq_l[BATCH * LATENT_DIM];
__device__ __align__(16) __nv_bfloat16 g_dw_h[INPUT_DIM * LATENT_DIM];
__device__ __align__(16) __nv_bfloat16 g_dw_l[INPUT_DIM * LATENT_DIM];

// ------------------------- helpers -----------------------------------------
__device__ __forceinline__ uint32_t smem_u32(const void* p) {
    uint32_t a;
    asm("{ .reg .u64 t; cvta.to.shared.u64 t, %1; cvt.u32.u64 %0, t; }" : "=r"(a) : "l"(p));
    return a;
}
__device__ __forceinline__ unsigned int float_key(float f) {
    unsigned int u = __float_as_uint(f);
    return (u & 0x80000000u) ? ~u : (u | 0x80000000u);
}
__device__ __forceinline__ float key_to_float(unsigned int k) {
    return (k & 0x80000000u) ? __uint_as_float(k ^ 0x80000000u)
                             : __uint_as_float(~k);
}
__device__ __forceinline__ void mma_bf16(float* d, const uint32_t* a, const uint32_t* b) {
    asm volatile(
        "mma.sync.aligned.m16n8k16.row.col.f32.bf16.bf16.f32 "
        "{%0,%1,%2,%3}, {%4,%5,%6,%7}, {%8,%9}, {%0,%1,%2,%3};"
        : "+f"(d[0]), "+f"(d[1]), "+f"(d[2]), "+f"(d[3])
        : "r"(a[0]), "r"(a[1]), "r"(a[2]), "r"(a[3]), "r"(b[0]), "r"(b[1]));
}
__device__ __forceinline__ void ldsm_x4(uint32_t& r0, uint32_t& r1,
                                        uint32_t& r2, uint32_t& r3, uint32_t addr) {
    asm volatile("ldmatrix.sync.aligned.m8n8.x4.shared.b16 {%0,%1,%2,%3}, [%4];"
                 : "=r"(r0), "=r"(r1), "=r"(r2), "=r"(r3) : "r"(addr));
}
__device__ __forceinline__ unsigned int pack_bf16x2(float lo, float hi) {
    __nv_bfloat162 h = __floats2bfloat162_rn(lo, hi);
    return *reinterpret_cast<unsigned int*>(&h);
}
__device__ __forceinline__ void split2(float v0, float v1,
                                       unsigned int& hw, unsigned int& lw) {
    __nv_bfloat16 h0 = __float2bfloat16(v0);
    __nv_bfloat16 h1 = __float2bfloat16(v1);
    float r0 = v0 - __bfloat162float(h0);
    float r1 = v1 - __bfloat162float(h1);
    __nv_bfloat162 hh; hh.x = h0; hh.y = h1;
    hw = *reinterpret_cast<unsigned int*>(&hh);
    lw = pack_bf16x2(r0, r1);
}

// ---------------------------------------------------------------------------
// init (merged): emb bf16 + inv-norm + counters + znorm2 reset; dec_w planes
// ---------------------------------------------------------------------------
__global__ void __launch_bounds__(256)
init_kernel(const float* __restrict__ emb, const float* __restrict__ dw) {
    const int warp = threadIdx.x >> 5, lane = threadIdx.x & 31;
    if (blockIdx.x < NUM_EMB / 8) {
        const int row = blockIdx.x * 8 + warp;
        const float4* p = reinterpret_cast<const float4*>(emb + (size_t)row * LATENT_DIM);
        float4 a = p[lane * 2], b = p[lane * 2 + 1];
        uint4 o;
        o.x = pack_bf16x2(a.x, a.y); o.y = pack_bf16x2(a.z, a.w);
        o.z = pack_bf16x2(b.x, b.y); o.w = pack_bf16x2(b.z, b.w);
        *reinterpret_cast<uint4*>(g_emb_bf16 + (size_t)row * LATENT_DIM + lane * 8) = o;
        float s = a.x*a.x + a.y*a.y + a.z*a.z + a.w*a.w
                + b.x*b.x + b.y*b.y + b.z*b.z + b.w*b.w;
        #pragma unroll
        for (int off = 16; off > 0; off >>= 1) s += __shfl_xor_sync(0xFFFFFFFFu, s, off);
        if (lane == 0) {
            g_inv_norm[row] = rsqrtf(s);
            g_amax[row]   = 0u;
            g_ccnt[row]   = 0u;
            g_znorm2[row] = 0.0f;          // BATCH == NUM_EMB
        }
    } else {
        const int row = (blockIdx.x - NUM_EMB / 8) * 8 + warp;
        const float4* p = reinterpret_cast<const float4*>(dw + (size_t)row * LATENT_DIM);
        float4 a = p[lane * 2], b = p[lane * 2 + 1];
        uint4 oh, ol;
        split2(a.x, a.y, oh.x, ol.x); split2(a.z, a.w, oh.y, ol.y);
        split2(b.x, b.y, oh.z, ol.z); split2(b.z, b.w, oh.w, ol.w);
        *reinterpret_cast<uint4*>(g_dw_h + (size_t)row * LATENT_DIM + lane * 8) = oh;
        *reinterpret_cast<uint4*>(g_dw_l + (size_t)row * LATENT_DIM + lane * 8) = ol;
    }
}

// ---------------------------------------------------------------------------
// encoder fp32 SIMT GEMM: CTA 128x64, per-thread 8x4.
// Fused epilogue: writes z fp32, z bf16, and partial |z|^2 (atomicAdd).
// ---------------------------------------------------------------------------
constexpr int EBK = 16, EBMP = 132, EBNP = 68;

__global__ void __launch_bounds__(256, 2)
sgemm_encoder(const float* __restrict__ A, const float* __restrict__ B,
              const float* __restrict__ bias, float* __restrict__ C,
              int M, int N, int K) {
    __shared__ __align__(16) float As[EBK * EBMP];
    __shared__ __align__(16) float Bs[EBK * EBNP];
    const int tid  = threadIdx.x;
    const int tx   = tid & 15;
    const int ty   = tid >> 4;
    const int row0 = blockIdx.y * 128;
    const int col0 = blockIdx.x * 64;
    float acc[8][4] = {};
    for (int k0 = 0; k0 < K; k0 += EBK) {
        #pragma unroll
        for (int it = 0; it < 2; it++) {
            int idx = tid + it * 256;
            int r   = idx >> 2;
            int kq  = (idx & 3) * 4;
            float4 v = *reinterpret_cast<const float4*>(&A[(size_t)(row0 + r) * K + k0 + kq]);
            As[(kq + 0) * EBMP + r] = v.x;
            As[(kq + 1) * EBMP + r] = v.y;
            As[(kq + 2) * EBMP + r] = v.z;
            As[(kq + 3) * EBMP + r] = v.w;
        }
        {
            int r  = tid >> 2;
            int kq = (tid & 3) * 4;
            float4 v = *reinterpret_cast<const float4*>(&B[(size_t)(col0 + r) * K + k0 + kq]);
            Bs[(kq + 0) * EBNP + r] = v.x;
            Bs[(kq + 1) * EBNP + r] = v.y;
            Bs[(kq + 2) * EBNP + r] = v.z;
            Bs[(kq + 3) * EBNP + r] = v.w;
        }
        __syncthreads();
        #pragma unroll
        for (int kk = 0; kk < EBK; kk++) {
            float rm[8], rn[4];
            float4 a0 = *reinterpret_cast<const float4*>(&As[kk * EBMP + ty * 8]);
            float4 a1 = *reinterpret_cast<const float4*>(&As[kk * EBMP + ty * 8 + 4]);
            float4 b0 = *reinterpret_cast<const float4*>(&Bs[kk * EBNP + tx * 4]);
            rm[0]=a0.x; rm[1]=a0.y; rm[2]=a0.z; rm[3]=a0.w;
            rm[4]=a1.x; rm[5]=a1.y; rm[6]=a1.z; rm[7]=a1.w;
            rn[0]=b0.x; rn[1]=b0.y; rn[2]=b0.z; rn[3]=b0.w;
            #pragma unroll
            for (int m = 0; m < 8; m++)
                #pragma unroll
                for (int n = 0; n < 4; n++)
                    acc[m][n] = fmaf(rm[m], rn[n], acc[m][n]);
        }
        __syncthreads();
    }
    int c = col0 + tx * 4;
    float4 bv = *reinterpret_cast<const float4*>(&bias[c]);
    #pragma unroll
    for (int m = 0; m < 8; m++) {
        int r = row0 + ty * 8 + m;
        float4 v;
        v.x = acc[m][0] + bv.x;
        v.y = acc[m][1] + bv.y;
        v.z = acc[m][2] + bv.z;
        v.w = acc[m][3] + bv.w;
        *reinterpret_cast<float4*>(&C[(size_t)r * N + c]) = v;
        // fused: bf16 z
        uint2 h;
        h.x = pack_bf16x2(v.x, v.y);
        h.y = pack_bf16x2(v.z, v.w);
        *reinterpret_cast<uint2*>(g_z_bf16 + (size_t)r * N + c) = h;
        // fused: partial |z|^2, reduced over the 16 tx lanes (half-warp)
        float sq = v.x*v.x + v.y*v.y + v.z*v.z + v.w*v.w;
        #pragma unroll
        for (int off = 8; off > 0; off >>= 1)
            sq += __shfl_xor_sync(0xFFFFFFFFu, sq, off);
        if (tx == 0) atomicAdd(&g_znorm2[r], sq);
    }
}

// ---------------------------------------------------------------------------
// shared tile constants + cp.async loader
// ---------------------------------------------------------------------------
constexpr int SKH  = 72;
constexpr int HBUF = 128 * SKH;

__device__ __forceinline__ void cp_chunk(const __nv_bfloat16* __restrict__ g,
                                         int gr0, int k0, __nv_bfloat16* sm, int tid) {
    #pragma unroll
    for (int it = 0; it < 4; it++) {
        int idx = tid + it * 256;
        int r   = idx >> 3;
        int c   = idx & 7;
        uint32_t dst = smem_u32(&sm[r * SKH + c * 8]);
        size_t src = __cvta_generic_to_global(g + (size_t)(gr0 + r) * 256 + k0 + c * 8);
        asm volatile("cp.async.ca.shared.global [%0], [%1], 16;" :: "r"(dst), "l"(src));
    }
}

// ---------------------------------------------------------------------------
// HMMA bf16 score GEMM — R10 8-warp config (best measured), ldmatrix loads
// ---------------------------------------------------------------------------
__global__ void __launch_bounds__(256, 2)
hmma_scores_kernel() {
    extern __shared__ __align__(16) __nv_bfloat16 dyn[];
    __nv_bfloat16* sA = dyn;
    __nv_bfloat16* sB = dyn + 2 * HBUF;
    __shared__ float s_inv[128];
    __shared__ float s_zinv[128];
    __shared__ unsigned int s_amax[128];

    const int tid = threadIdx.x, wid = tid >> 5, lane = tid & 31;
    const int row0 = blockIdx.y * 128, col0 = blockIdx.x * 128;
    const int wm = (wid & 3) * 32, wn = (wid >> 2) * 64;
    const int g = lane >> 2, q = lane & 3;

    const int lane7 = lane & 7;
    const int a_row = wm + lane7 + ((lane >> 3) & 1) * 8;
    const int a_col = (lane >> 4) * 8;
    const int b_row = wn + lane7 + (lane >> 4) * 8;
    const int b_col = ((lane >> 3) & 1) * 8;

    if (tid < 128) {
        s_inv[tid]  = g_inv_norm[col0 + tid];
        s_zinv[tid] = rsqrtf(g_znorm2[row0 + tid]);
        s_amax[tid] = 0u;
    }

    cp_chunk(g_z_bf16,   row0, 0, sA, tid);
    cp_chunk(g_emb_bf16, col0, 0, sB, tid);
    asm volatile("cp.async.commit_group;" ::: "memory");

    float acc[2][8][4] = {};
    #pragma unroll
    for (int kc = 0; kc < 4; kc++) {
        if (kc < 3) {
            cp_chunk(g_z_bf16,   row0, (kc + 1) * 64, sA + ((kc + 1) & 1) * HBUF, tid);
            cp_chunk(g_emb_bf16, col0, (kc + 1) * 64, sB + ((kc + 1) & 1) * HBUF, tid);
            asm volatile("cp.async.commit_group;" ::: "memory");
            asm volatile("cp.async.wait_group 1;" ::: "memory");
        } else {
            asm volatile("cp.async.wait_group 0;" ::: "memory");
        }
        __syncthreads();

        const uint32_t aBase = smem_u32(sA + (kc & 1) * HBUF);
        const uint32_t bBase = smem_u32(sB + (kc & 1) * HBUF);
        #pragma unroll
        for (int k16 = 0; k16 < 4; k16++) {
            uint32_t a[2][4];
            #pragma unroll
            for (int mf = 0; mf < 2; mf++)
                ldsm_x4(a[mf][0], a[mf][1], a[mf][2], a[mf][3],
                        aBase + ((a_row + mf * 16) * SKH + k16 * 16 + a_col) * 2);
            uint32_t b[8][2];
            #pragma unroll
            for (int p = 0; p < 4; p++)
                ldsm_x4(b[2*p][0], b[2*p][1], b[2*p+1][0], b[2*p+1][1],
                        bBase + ((b_row + p * 16) * SKH + k16 * 16 + b_col) * 2);
            #pragma unroll
            for (int mf = 0; mf < 2; mf++)
                #pragma unroll
                for (int nf = 0; nf < 8; nf++)
                    mma_bf16(acc[mf][nf], a[mf], b[nf]);
        }
        __syncthreads();
    }

    #pragma unroll
    for (int mf = 0; mf < 2; mf++) {
        #pragma unroll
        for (int rp = 0; rp < 2; rp++) {
            int lrow = wm + mf * 16 + g + rp * 8;
            float zi = s_zinv[lrow];
            unsigned int bestk = 0u;
            #pragma unroll
            for (int nf = 0; nf < 8; nf++) {
                int lcol = wn + nf * 8 + q * 2;
                float s0 = acc[mf][nf][rp * 2 + 0] * s_inv[lcol + 0] * zi;
                float s1 = acc[mf][nf][rp * 2 + 1] * s_inv[lcol + 1] * zi;
                unsigned int k0 = float_key(s0), k1 = float_key(s1);
                bestk = bestk > k0 ? bestk : k0;
                bestk = bestk > k1 ? bestk : k1;
            }
            unsigned int o1 = __shfl_xor_sync(0xFFFFFFFFu, bestk, 1);
            bestk = bestk > o1 ? bestk : o1;
            unsigned int o2 = __shfl_xor_sync(0xFFFFFFFFu, bestk, 2);
            bestk = bestk > o2 ? bestk : o2;
            if (q == 0) atomicMax(&s_amax[lrow], bestk);
        }
    }
    __syncthreads();

    if (tid < 128) {
        unsigned int old = atomicMax(&g_amax[row0 + tid], s_amax[tid]);
        if (old > s_amax[tid]) s_amax[tid] = old;
    }
    __syncthreads();

    #pragma unroll
    for (int mf = 0; mf < 2; mf++) {
        #pragma unroll
        for (int rp = 0; rp < 2; rp++) {
            int lrow = wm + mf * 16 + g + rp * 8;
            int grow = row0 + lrow;
            float zi = s_zinv[lrow];
            float lth = key_to_float(s_amax[lrow]) - MARGIN;
            #pragma unroll
            for (int nf = 0; nf < 8; nf++) {
                int lcol = wn + nf * 8 + q * 2;
                #pragma unroll
                for (int h = 0; h < 2; h++) {
                    float s = acc[mf][nf][rp * 2 + h] * s_inv[lcol + h] * zi;
                    if (s >= lth) {
                        unsigned int pos = atomicAdd(&g_ccnt[grow], 1u);
                        if (pos < CAP)
                            g_cand[(size_t)grow * CAP + pos] =
                                make_uint2(__float_as_uint(s), (unsigned)(col0 + lcol + h));
                    }
                }
            }
        }
    }
}

// ---------------------------------------------------------------------------
// select: candidate filter + exact fp32 rescore + gather + zq hi/lo planes
// ---------------------------------------------------------------------------
__device__ __forceinline__ unsigned long long
warp_rescore(int k, const float* __restrict__ emb,
             float4 zf0, float4 zf1, int lane) {
    const float4* e = reinterpret_cast<const float4*>(emb + (size_t)k * LATENT_DIM);
    float4 e0 = e[lane * 2], e1 = e[lane * 2 + 1];
    float d = e0.x*zf0.x + e0.y*zf0.y + e0.z*zf0.z + e0.w*zf0.w
            + e1.x*zf1.x + e1.y*zf1.y + e1.z*zf1.z + e1.w*zf1.w;
    #pragma unroll
    for (int off = 16; off > 0; off >>= 1)
        d += __shfl_xor_sync(0xFFFFFFFFu, d, off);
    float cosv = d * g_inv_norm[k];
    return ((unsigned long long)float_key(cosv) << 32) |
           (unsigned long long)(0xFFFFFFFFu - (unsigned)k);
}

__global__ void __launch_bounds__(256)
select_gather_kernel(const float* __restrict__ z, const float* __restrict__ emb,
                     float* __restrict__ zq_out, float* __restrict__ idx_out) {
    const int warp = threadIdx.x >> 5, lane = threadIdx.x & 31;
    const int row  = blockIdx.x * 8 + warp;

    const float4* zrow = reinterpret_cast<const float4*>(z + (size_t)row * LATENT_DIM);
    float4 zf0 = zrow[lane * 2], zf1 = zrow[lane * 2 + 1];

    float maxf = key_to_float(g_amax[row]);
    float thresh = maxf - MARGIN;
    unsigned int cnt = g_ccnt[row];
    bool fullscan = !(thresh >= -4.0f) || !(thresh <= 1.0f) || (cnt > CAP);

    unsigned long long best = 0ull;
    if (!fullscan) {
        const uint2* clist = g_cand + (size_t)row * CAP;
        for (unsigned int base = 0; base < cnt; base += 32) {
            unsigned int i = base + lane;
            unsigned int col = 0; bool cand = false;
            if (i < cnt) {
                uint2 e = clist[i];
                float s = __uint_as_float(e.x);
                if (!(s < thresh)) { cand = true; col = e.y; }
            }
            unsigned int m = __ballot_sync(0xFFFFFFFFu, cand);
            while (m) {
                int src = __ffs(m) - 1; m &= m - 1;
                int k = (int)__shfl_sync(0xFFFFFFFFu, col, src);
                unsigned long long key = warp_rescore(k, emb, zf0, zf1, lane);
                best = best > key ? best : key;
            }
        }
    } else {
        for (int k = 0; k < NUM_EMB; k++) {
            unsigned long long key = warp_rescore(k, emb, zf0, zf1, lane);
            best = best > key ? best : key;
        }
    }

    unsigned int widx = 0xFFFFFFFFu - (unsigned int)(best & 0xFFFFFFFFull);
    if (widx >= NUM_EMB) widx = 0;
    if (lane == 0) idx_out[row] = (float)widx;

    const float4* e = reinterpret_cast<const float4*>(emb + (size_t)widx * LATENT_DIM);
    float4 e0 = e[lane * 2], e1 = e[lane * 2 + 1];
    float4* dst = reinterpret_cast<float4*>(zq_out + (size_t)row * LATENT_DIM);
    dst[lane * 2]     = e0;
    dst[lane * 2 + 1] = e1;
    uint4 oh, ol;
    split2(e0.x, e0.y, oh.x, ol.x); split2(e0.z, e0.w, oh.y, ol.y);
    split2(e1.x, e1.y, oh.z, ol.z); split2(e1.z, e1.w, oh.w, ol.w);
    *reinterpret_cast<uint4*>(g_zq_h + (size_t)row * LATENT_DIM + lane * 8) = oh;
    *reinterpret_cast<uint4*>(g_zq_l + (size_t)row * LATENT_DIM + lane * 8) = ol;
}

// ---------------------------------------------------------------------------
// decoder: 3-pass split-bf16 HMMA (ah*bh + al*bh + ah*bl), ldmatrix (R10 form)
// ---------------------------------------------------------------------------
__global__ void __launch_bounds__(256, 2)
hmma_decoder_kernel(const float* __restrict__ bias, float* __restrict__ C) {
    extern __shared__ __align__(16) __nv_bfloat16 dyn[];
    __nv_bfloat16* sAh = dyn;
    __nv_bfloat16* sAl = dyn + HBUF;
    __nv_bfloat16* sBh = dyn + 2 * HBUF;
    __nv_bfloat16* sBl = dyn + 3 * HBUF;
    __shared__ float s_bias[128];

    const int tid = threadIdx.x, wid = tid >> 5, lane = tid & 31;
    const int row0 = blockIdx.y * 128, col0 = blockIdx.x * 128;
    const int wm = (wid & 3) * 32, wn = (wid >> 2) * 64;
    const int g = lane >> 2, q = lane & 3;

    const int lane7 = lane & 7;
    const int a_row = wm + lane7 + ((lane >> 3) & 1) * 8;
    const int a_col = (lane >> 4) * 8;
    const int b_row = wn + lane7 + (lane >> 4) * 8;
    const int b_col = ((lane >> 3) & 1) * 8;

    if (tid < 128) s_bias[tid] = bias[col0 + tid];

    const uint32_t ahB = smem_u32(sAh), alB = smem_u32(sAl);
    const uint32_t bhB = smem_u32(sBh), blB = smem_u32(sBl);

    float acc[2][8][4] = {};
    #pragma unroll
    for (int kc = 0; kc < 4; kc++) {
        cp_chunk(g_zq_h, row0, kc * 64, sAh, tid);
        cp_chunk(g_zq_l, row0, kc * 64, sAl, tid);
        cp_chunk(g_dw_h, col0, kc * 64, sBh, tid);
        cp_chunk(g_dw_l, col0, kc * 64, sBl, tid);
        asm volatile("cp.async.commit_group;" ::: "memory");
        asm volatile("cp.async.wait_group 0;" ::: "memory");
        __syncthreads();

        #pragma unroll
        for (int k16 = 0; k16 < 4; k16++) {
            uint32_t ah[2][4], al[2][4];
            #pragma unroll
            for (int mf = 0; mf < 2; mf++) {
                uint32_t off = ((a_row + mf * 16) * SKH + k16 * 16 + a_col) * 2;
                ldsm_x4(ah[mf][0], ah[mf][1], ah[mf][2], ah[mf][3], ahB + off);
                ldsm_x4(al[mf][0], al[mf][1], al[mf][2], al[mf][3], alB + off);
            }
            uint32_t b[8][2];
            #pragma unroll
            for (int p = 0; p < 4; p++)
                ldsm_x4(b[2*p][0], b[2*p][1], b[2*p+1][0], b[2*p+1][1],
                        bhB + ((b_row + p * 16) * SKH + k16 * 16 + b_col) * 2);
            #pragma unroll
            for (int mf = 0; mf < 2; mf++)
                #pragma unroll
                for (int nf = 0; nf < 8; nf++) {
                    mma_bf16(acc[mf][nf], ah[mf], b[nf]);
                    mma_bf16(acc[mf][nf], al[mf], b[nf]);
                }
            #pragma unroll
            for (int p = 0; p < 4; p++)
                ldsm_x4(b[2*p][0], b[2*p][1], b[2*p+1][0], b[2*p+1][1],
                        blB + ((b_row + p * 16) * SKH + k16 * 16 + b_col) * 2);
            #pragma unroll
            for (int mf = 0; mf < 2; mf++)
                #pragma unroll
                for (int nf = 0; nf < 8; nf++)
                    mma_bf16(acc[mf][nf], ah[mf], b[nf]);
        }
        __syncthreads();
    }

    #pragma unroll
    for (int mf = 0; mf < 2; mf++) {
        #pragma unroll
        for (int rp = 0; rp < 2; rp++) {
            int grow = row0 + wm + mf * 16 + g + rp * 8;
            float* out = C + (size_t)grow * INPUT_DIM + col0;
            #pragma unroll
            for (int nf = 0; nf < 8; nf++) {
                int lcol = wn + nf * 8 + q * 2;
                float2 v;
                v.x = acc[mf][nf][rp * 2 + 0] + s_bias[lcol + 0];
                v.y = acc[mf][nf][rp * 2 + 1] + s_bias[lcol + 1];
                *reinterpret_cast<float2*>(out + lcol) = v;
            }
        }
    }
}

// ---------------------------------------------------------------------------
// launch (single stream, R10 structure, convert_z fused into encoder)
// ---------------------------------------------------------------------------
extern "C" void kernel_launch(void* const* d_in, const int* in_sizes, int n_in,
                              void* d_out, int out_size) {
    const float* x     = (const float*)d_in[0];
    const float* enc_w = (const float*)d_in[1];
    const float* enc_b = (const float*)d_in[2];
    const float* emb   = (const float*)d_in[3];
    const float* dec_w = (const float*)d_in[4];
    const float* dec_b = (const float*)d_in[5];

    float* out     = (float*)d_out;
    float* x_recon = out;
    float* z       = x_recon + (size_t)BATCH * INPUT_DIM;
    float* zq      = z + (size_t)BATCH * LATENT_DIM;
    float* idxf    = zq + (size_t)BATCH * LATENT_DIM;

    const int HSMEM = 4 * HBUF * (int)sizeof(__nv_bfloat16);   // 73728 B
    cudaFuncSetAttribute(hmma_scores_kernel,
                         cudaFuncAttributeMaxDynamicSharedMemorySize, HSMEM);
    cudaFuncSetAttribute(hmma_decoder_kernel,
                         cudaFuncAttributeMaxDynamicSharedMemorySize, HSMEM);

    // 0) emb bf16 + inv-norms + counters + znorm2 reset; dec_w hi/lo planes
    init_kernel<<<NUM_EMB / 8 + INPUT_DIM / 8, 256>>>(emb, dec_w);

    // 1) encoder (fp32 SIMT, fused z->bf16 + |z|^2): z = x @ enc_w^T + enc_b
    sgemm_encoder<<<dim3(LATENT_DIM / 64, BATCH / 128), 256>>>(
        x, enc_w, enc_b, z, BATCH, LATENT_DIM, INPUT_DIM);

    // 2) HMMA bf16 cosine scores -> per-row max + candidate lists
    hmma_scores_kernel<<<dim3(NUM_EMB / 128, BATCH / 128), 256, HSMEM>>>();

    // 3) candidate filter + exact fp32 rescore + argmin + gather (+ zq planes)
    select_gather_kernel<<<BATCH / 8, 256>>>(z, emb, zq, idxf);

    // 4) decoder (3-pass split-bf16 HMMA): x_recon = z_q @ dec_w^T + dec_b
    hmma_decoder_kernel<<<dim3(INPUT_DIM / 128, BATCH / 128), 256, HSMEM>>>(
        dec_b, x_recon);
}